// round 4
// baseline (speedup 1.0000x reference)
#include <cuda_runtime.h>

typedef unsigned long long ull;

// ---------------- scratch (device globals; no allocation allowed) ----------------
__device__ float g_Wp[192 * 128];                       // permutation-adjusted W
__device__ float g_Tu[(size_t)500000 * 128];            // user table  (256 MB)
__device__ float g_Ti[(size_t)100000 * 128];            // item table  (51 MB)
__device__ int   g_is64;                                // adj dtype flag
__device__ int   g_swap;                                // adjA/adjB swap flag

// ---------------- threefry2x32 core ----------------
__device__ __forceinline__ unsigned rotl32(unsigned x, int d) {
    return (x << d) | (x >> (32 - d));
}

__device__ void threefry2x32(unsigned k0, unsigned k1, unsigned& x0, unsigned& x1) {
    unsigned k2 = k0 ^ k1 ^ 0x1BD11BDAu;
    x0 += k0; x1 += k1;
    const int R0[4] = {13, 15, 26, 6};
    const int R1[4] = {17, 29, 16, 24};
#pragma unroll
    for (int i = 0; i < 4; i++) { x0 += x1; x1 = rotl32(x1, R0[i]); x1 ^= x0; }
    x0 += k1; x1 += k2 + 1u;
#pragma unroll
    for (int i = 0; i < 4; i++) { x0 += x1; x1 = rotl32(x1, R1[i]); x1 ^= x0; }
    x0 += k2; x1 += k0 + 2u;
#pragma unroll
    for (int i = 0; i < 4; i++) { x0 += x1; x1 = rotl32(x1, R0[i]); x1 ^= x0; }
    x0 += k0; x1 += k1 + 3u;
#pragma unroll
    for (int i = 0; i < 4; i++) { x0 += x1; x1 = rotl32(x1, R1[i]); x1 ^= x0; }
    x0 += k1; x1 += k2 + 4u;
#pragma unroll
    for (int i = 0; i < 4; i++) { x0 += x1; x1 = rotl32(x1, R0[i]); x1 ^= x0; }
    x0 += k2; x1 += k0 + 5u;
}

// ---------------- K0: jax PARTITIONABLE threefry -> reordered W, + probes -------
__global__ void k_build_wp(const float* __restrict__ W,
                           const void* __restrict__ adjA) {
    __shared__ unsigned bits[2][64];
    __shared__ unsigned subk[2][2];
    __shared__ int src[192];
    const int t = threadIdx.x;
    const int s = (t < 128) ? (t >> 6) : -1;   // seed group: 0->42, 1->43
    const int i = t & 63;

    if (t < 192) src[t] = t;                   // review block stays identity

    if (t < 2) {                               // foldlike split: subkey = TF(key,(0,1))
        unsigned x0 = 0u, x1 = 1u;
        threefry2x32(0u, 42u + (unsigned)t, x0, x1);
        subk[t][0] = x0; subk[t][1] = x1;
    }
    if (t == 128) {  // int64 vs int32 probe: odd int32 slots all zero => int64
        const int* p = (const int*)adjA;
        int all0 = 1;
        for (int j = 1; j < 128; j += 2) all0 &= (p[j] == 0);
        g_is64 = all0;
    }
    __syncthreads();
    if (t == 129) {  // adjA has values >= 100000 => adjA is adj_u (no swap)
        int big = 0;
        if (g_is64) {
            const long long* a = (const long long*)adjA;
            for (int j = 0; j < 4096; j++) big |= (a[j] >= 100000);
        } else {
            const int* a = (const int*)adjA;
            for (int j = 0; j < 4096; j++) big |= (a[j] >= 100000);
        }
        g_swap = !big;
    }

    if (s >= 0) {   // partitionable random_bits: counter (0, i), output x0^x1
        unsigned x0 = 0u, x1 = (unsigned)i;
        threefry2x32(subk[s][0], subk[s][1], x0, x1);
        bits[s][i] = x0 ^ x1;
    }
    __syncthreads();

    if (s >= 0) {   // stable rank; Wp[block+i] = W[block+rank_i]
        unsigned kv = bits[s][i];
        int r = 0;
        for (int j = 0; j < 64; j++) {
            unsigned kj = bits[s][j];
            r += (kj < kv) || (kj == kv && j < i);
        }
        src[(s + 1) * 64 + i] = (s + 1) * 64 + r;
    }
    __syncthreads();

    for (int idx = t; idx < 192 * 128; idx += blockDim.x)
        g_Wp[idx] = W[src[idx >> 7] * 128 + (idx & 127)];
}

// ---------------- packed f32x2 helpers ----------------
__device__ __forceinline__ ull pk2(float x, float y) {
    ull r; asm("mov.b64 %0, {%1, %2};" : "=l"(r) : "f"(x), "f"(y)); return r;
}
__device__ __forceinline__ float2 upk2(ull v) {
    float2 f; asm("mov.b64 {%0, %1}, %2;" : "=f"(f.x), "=f"(f.y) : "l"(v)); return f;
}
__device__ __forceinline__ ull fma2_(ull a, ull b, ull c) {
    ull d; asm("fma.rn.f32x2 %0, %1, %2, %3;" : "=l"(d) : "l"(a), "l"(b), "l"(c)); return d;
}
__device__ __forceinline__ void pf_l2(const void* p) {
    asm volatile("prefetch.global.L2 [%0];" :: "l"(p));
}

// ---------------- GEMM: C[M,128] = A[M,64] @ g_Wp[koff:koff+64, :] (+ epilogue) ----
// MODE 0: A=item  -> g_Ti               (koff=128)
// MODE 1: A=user  -> g_Tu               (koff=64)
// MODE 2: A=review-> out = relu(. + g_Tu[adj_u] + g_Ti[adj_i])   (koff=0)
// Block: 128 threads, tile 64 rows x 128 cols; thread = 8 rows x 8 cols.
// A read directly from global (warp-broadcast addresses, L1-served); B from smem.
template <int MODE>
__global__ __launch_bounds__(128, 4)
void k_gemm(const float* __restrict__ A, int M, float* __restrict__ Cout,
            const void* __restrict__ adjA, const void* __restrict__ adjB) {
    constexpr int KOFF = (MODE == 2) ? 0 : (MODE == 1 ? 64 : 128);

    __shared__ __align__(16) float Bs[64 * 128];   // 32 KB
    __shared__ int s_au[64], s_ai[64];

    const int t = threadIdx.x;
    const int row0 = blockIdx.x * 64;
    const int tx = t & 15, ty = t >> 4;
    const int c0 = tx * 8, r0 = ty * 8;

    // load full B block (64x128) once
    {
        const float4* src4 = (const float4*)(g_Wp + KOFF * 128);
        float4* b4 = (float4*)Bs;
#pragma unroll
        for (int i = 0; i < 16; i++) b4[i * 128 + t] = src4[i * 128 + t];
    }
    // gather indices + L2 prefetch of table rows (hidden behind mainloop)
    if (MODE == 2) {
        int lr = t & 63;
        int gr = min(row0 + lr, M - 1);
        if (t < 64) {
            const void* aU = g_swap ? adjB : adjA;
            int idx = g_is64 ? (int)((const long long*)aU)[gr]
                             : ((const int*)aU)[gr];
            s_au[lr] = idx;
            const char* p = (const char*)(g_Tu + ((size_t)idx << 7));
#pragma unroll
            for (int l = 0; l < 4; l++) pf_l2(p + l * 128);
        } else {
            const void* aI = g_swap ? adjA : adjB;
            int idx = g_is64 ? (int)((const long long*)aI)[gr]
                             : ((const int*)aI)[gr];
            s_ai[lr] = idx;
            const char* p = (const char*)(g_Ti + ((size_t)idx << 7));
#pragma unroll
            for (int l = 0; l < 4; l++) pf_l2(p + l * 128);
        }
    }

    // per-thread A row pointers (clamped; stores are guarded later)
    const float4* arow[8];
#pragma unroll
    for (int i = 0; i < 8; i++) {
        int gr = min(row0 + r0 + i, M - 1);
        arow[i] = (const float4*)(A + (size_t)gr * 64);
    }

    ull acc[8][4];
#pragma unroll
    for (int i = 0; i < 8; i++)
#pragma unroll
        for (int j = 0; j < 4; j++) acc[i][j] = 0ull;

    __syncthreads();   // Bs + s_au/s_ai ready

    // mainloop: 16 panels of 4 k
#pragma unroll 1
    for (int kp = 0; kp < 16; kp++) {
        float4 a[8];
#pragma unroll
        for (int i = 0; i < 8; i++) a[i] = arow[i][kp];
#pragma unroll
        for (int j = 0; j < 4; j++) {
            const float* brow = Bs + (kp * 4 + j) * 128 + c0;
            ulonglong2 bA = *(const ulonglong2*)(brow);
            ulonglong2 bB = *(const ulonglong2*)(brow + 4);
#pragma unroll
            for (int i = 0; i < 8; i++) {
                float av = (j == 0) ? a[i].x : (j == 1) ? a[i].y
                         : (j == 2) ? a[i].z : a[i].w;
                ull ad = pk2(av, av);
                acc[i][0] = fma2_(ad, bA.x, acc[i][0]);
                acc[i][1] = fma2_(ad, bA.y, acc[i][1]);
                acc[i][2] = fma2_(ad, bB.x, acc[i][2]);
                acc[i][3] = fma2_(ad, bB.y, acc[i][3]);
            }
        }
    }

    // epilogue
#pragma unroll
    for (int i = 0; i < 8; i++) {
        int lr = r0 + i;
        int gr = row0 + lr;
        if (gr >= M) continue;
        float2 p0 = upk2(acc[i][0]), p1 = upk2(acc[i][1]);
        float2 p2 = upk2(acc[i][2]), p3 = upk2(acc[i][3]);
        if (MODE == 2) {
            const float4* tu = (const float4*)(g_Tu + ((size_t)s_au[lr] << 7) + c0);
            const float4* ti = (const float4*)(g_Ti + ((size_t)s_ai[lr] << 7) + c0);
            float4 u0 = tu[0], u1 = tu[1];
            float4 v0 = ti[0], v1 = ti[1];
            float4 o0, o1;
            o0.x = fmaxf(p0.x + u0.x + v0.x, 0.f);
            o0.y = fmaxf(p0.y + u0.y + v0.y, 0.f);
            o0.z = fmaxf(p1.x + u0.z + v0.z, 0.f);
            o0.w = fmaxf(p1.y + u0.w + v0.w, 0.f);
            o1.x = fmaxf(p2.x + u1.x + v1.x, 0.f);
            o1.y = fmaxf(p2.y + u1.y + v1.y, 0.f);
            o1.z = fmaxf(p3.x + u1.z + v1.z, 0.f);
            o1.w = fmaxf(p3.y + u1.w + v1.w, 0.f);
            float4* dst = (float4*)(Cout + ((size_t)gr << 7) + c0);
            dst[0] = o0; dst[1] = o1;
        } else {
            float* T = (MODE == 0) ? g_Ti : g_Tu;
            float4 o0 = make_float4(p0.x, p0.y, p1.x, p1.y);
            float4 o1 = make_float4(p2.x, p2.y, p3.x, p3.y);
            float4* dst = (float4*)(T + ((size_t)gr << 7) + c0);
            dst[0] = o0; dst[1] = o1;
        }
    }
}

// ---------------- launch ----------------
extern "C" void kernel_launch(void* const* d_in, const int* in_sizes, int n_in,
                              void* d_out, int out_size) {
    // classify inputs by element count (robust to metadata ordering)
    const float *review = nullptr, *user = nullptr, *item = nullptr, *W = nullptr;
    const void *adjA = nullptr, *adjB = nullptr;
    int n_r = 1000000, n_u = 500000, n_i = 100000;
    for (int k = 0; k < n_in; k++) {
        long long sz = in_sizes[k];
        if (sz == 64000000)      { review = (const float*)d_in[k]; n_r = (int)(sz / 64); }
        else if (sz == 32000000) { user   = (const float*)d_in[k]; n_u = (int)(sz / 64); }
        else if (sz == 6400000)  { item   = (const float*)d_in[k]; n_i = (int)(sz / 64); }
        else if (sz == 24576)    { W      = (const float*)d_in[k]; }
        else if (!adjA)          { adjA   = d_in[k]; }
        else                     { adjB   = d_in[k]; }
    }
    // fallback to declared order if classification failed
    if (!review || !user || !item || !W || !adjA || !adjB) {
        review = (const float*)d_in[0]; user = (const float*)d_in[1];
        item   = (const float*)d_in[2]; W    = (const float*)d_in[3];
        adjA   = d_in[4];               adjB = d_in[5];
        n_r = in_sizes[0] / 64; n_u = in_sizes[1] / 64; n_i = in_sizes[2] / 64;
    }
    float* out = (float*)d_out;

    k_build_wp<<<1, 256>>>(W, adjA);
    k_gemm<0><<<(n_i + 63) / 64, 128>>>(item,   n_i, nullptr, nullptr, nullptr);
    k_gemm<1><<<(n_u + 63) / 64, 128>>>(user,   n_u, nullptr, nullptr, nullptr);
    k_gemm<2><<<(n_r + 63) / 64, 128>>>(review, n_r, out,     adjA,    adjB);
}

// round 5
// speedup vs baseline: 1.1191x; 1.1191x over previous
#include <cuda_runtime.h>

typedef unsigned long long ull;

// ---------------- scratch (device globals; no allocation allowed) ----------------
__device__ float g_Wp[192 * 128];                       // permutation-adjusted W
__device__ float g_Tu[(size_t)500000 * 128];            // user table  (256 MB)
__device__ float g_Ti[(size_t)100000 * 128];            // item table  (51 MB)
__device__ int   g_is64;                                // adj dtype flag
__device__ int   g_swap;                                // adjA/adjB swap flag

// ---------------- threefry2x32 core ----------------
__device__ __forceinline__ unsigned rotl32(unsigned x, int d) {
    return (x << d) | (x >> (32 - d));
}

__device__ void threefry2x32(unsigned k0, unsigned k1, unsigned& x0, unsigned& x1) {
    unsigned k2 = k0 ^ k1 ^ 0x1BD11BDAu;
    x0 += k0; x1 += k1;
    const int R0[4] = {13, 15, 26, 6};
    const int R1[4] = {17, 29, 16, 24};
#pragma unroll
    for (int i = 0; i < 4; i++) { x0 += x1; x1 = rotl32(x1, R0[i]); x1 ^= x0; }
    x0 += k1; x1 += k2 + 1u;
#pragma unroll
    for (int i = 0; i < 4; i++) { x0 += x1; x1 = rotl32(x1, R1[i]); x1 ^= x0; }
    x0 += k2; x1 += k0 + 2u;
#pragma unroll
    for (int i = 0; i < 4; i++) { x0 += x1; x1 = rotl32(x1, R0[i]); x1 ^= x0; }
    x0 += k0; x1 += k1 + 3u;
#pragma unroll
    for (int i = 0; i < 4; i++) { x0 += x1; x1 = rotl32(x1, R1[i]); x1 ^= x0; }
    x0 += k1; x1 += k2 + 4u;
#pragma unroll
    for (int i = 0; i < 4; i++) { x0 += x1; x1 = rotl32(x1, R0[i]); x1 ^= x0; }
    x0 += k2; x1 += k0 + 5u;
}

// ---------------- K0: jax PARTITIONABLE threefry -> reordered W, + probes -------
__global__ void k_build_wp(const float* __restrict__ W,
                           const void* __restrict__ adjA) {
    __shared__ unsigned bits[2][64];
    __shared__ unsigned subk[2][2];
    __shared__ int src[192];
    const int t = threadIdx.x;
    const int s = (t < 128) ? (t >> 6) : -1;   // seed group: 0->42, 1->43
    const int i = t & 63;

    if (t < 192) src[t] = t;                   // review block stays identity

    if (t < 2) {                               // foldlike split: subkey = TF(key,(0,1))
        unsigned x0 = 0u, x1 = 1u;
        threefry2x32(0u, 42u + (unsigned)t, x0, x1);
        subk[t][0] = x0; subk[t][1] = x1;
    }
    if (t == 128) {  // int64 vs int32 probe: odd int32 slots all zero => int64
        const int* p = (const int*)adjA;
        int all0 = 1;
        for (int j = 1; j < 128; j += 2) all0 &= (p[j] == 0);
        g_is64 = all0;
    }
    __syncthreads();
    if (t == 129) {  // adjA has values >= 100000 => adjA is adj_u (no swap)
        int big = 0;
        if (g_is64) {
            const long long* a = (const long long*)adjA;
            for (int j = 0; j < 4096; j++) big |= (a[j] >= 100000);
        } else {
            const int* a = (const int*)adjA;
            for (int j = 0; j < 4096; j++) big |= (a[j] >= 100000);
        }
        g_swap = !big;
    }

    if (s >= 0) {   // partitionable random_bits: counter (0, i), output x0^x1
        unsigned x0 = 0u, x1 = (unsigned)i;
        threefry2x32(subk[s][0], subk[s][1], x0, x1);
        bits[s][i] = x0 ^ x1;
    }
    __syncthreads();

    if (s >= 0) {   // stable rank; Wp[block+i] = W[block+rank_i]
        unsigned kv = bits[s][i];
        int r = 0;
        for (int j = 0; j < 64; j++) {
            unsigned kj = bits[s][j];
            r += (kj < kv) || (kj == kv && j < i);
        }
        src[(s + 1) * 64 + i] = (s + 1) * 64 + r;
    }
    __syncthreads();

    for (int idx = t; idx < 192 * 128; idx += blockDim.x)
        g_Wp[idx] = W[src[idx >> 7] * 128 + (idx & 127)];
}

// ---------------- packed f32x2 helpers ----------------
__device__ __forceinline__ ull pk2(float x, float y) {
    ull r; asm("mov.b64 %0, {%1, %2};" : "=l"(r) : "f"(x), "f"(y)); return r;
}
__device__ __forceinline__ float2 upk2(ull v) {
    float2 f; asm("mov.b64 {%0, %1}, %2;" : "=f"(f.x), "=f"(f.y) : "l"(v)); return f;
}
__device__ __forceinline__ ull fma2_(ull a, ull b, ull c) {
    ull d; asm("fma.rn.f32x2 %0, %1, %2, %3;" : "=l"(d) : "l"(a), "l"(b), "l"(c)); return d;
}
__device__ __forceinline__ void pf_l2(const void* p) {
    asm volatile("prefetch.global.L2 [%0];" :: "l"(p));
}

// ---------------- GEMM: C[M,128] = A[M,64] @ g_Wp[koff:koff+64, :] (+ epilogue) ----
// MODE 0: A=item  -> g_Ti   (koff=128)     MODE 1: A=user -> g_Tu  (koff=64)
// MODE 2: A=review-> out = relu(. + g_Tu[adj_u] + g_Ti[adj_i])     (koff=0)
// Block 128 thr, tile 64r x 128c, thread 8x8.
// Bs lane-permuted: col c=g*8+j stored at k*128 + (j>=4)*64 + g*4 + (j&3)
//   -> each thread float4 B load is contiguous across tx lanes (2 wf/instr).
// At transposed, stride 72 (16B aligned) -> A = 2x LDS.128, 1 wf each.
template <int MODE>
__global__ __launch_bounds__(128, 4)
void k_gemm(const float* __restrict__ A, int M, float* __restrict__ Cout,
            const void* __restrict__ adjA, const void* __restrict__ adjB) {
    constexpr int KOFF = (MODE == 2) ? 0 : (MODE == 1 ? 64 : 128);
    constexpr int ATS = 72;   // At stride in floats

    __shared__ __align__(16) float Bs[64 * 128];   // 32 KB (permuted layout)
    __shared__ __align__(16) float At[32 * ATS];   // 9.2 KB, transposed A chunk
    __shared__ int s_au[64], s_ai[64];

    const int t = threadIdx.x;
    const int row0 = blockIdx.x * 64;
    const int tx = t & 15, ty = t >> 4;
    const int c0 = tx * 8, r0 = ty * 8;

    // ---- stage B (permuted) ----
    {
        const float4* w4 = (const float4*)(g_Wp + KOFF * 128);
#pragma unroll
        for (int it = 0; it < 16; it++) {
            int idx = it * 128 + t;            // 0..2047 float4 tasks
            int k = idx >> 5, m = idx & 31;    // m = source float4 within row
            float4 v = w4[idx];
            // dest float position: k*128 + (m&1)*64 + (m>>1)*4
            *(float4*)(Bs + k * 128 + (m & 1) * 64 + (m >> 1) * 4) = v;
        }
    }
    // ---- gather indices + L2 prefetch ----
    if (MODE == 2) {
        int lr = t & 63;
        int gr = min(row0 + lr, M - 1);
        if (t < 64) {
            const void* aU = g_swap ? adjB : adjA;
            int idx = g_is64 ? (int)((const long long*)aU)[gr]
                             : ((const int*)aU)[gr];
            s_au[lr] = idx;
            const char* p = (const char*)(g_Tu + ((size_t)idx << 7));
#pragma unroll
            for (int l = 0; l < 4; l++) pf_l2(p + l * 128);
        } else {
            const void* aI = g_swap ? adjA : adjB;
            int idx = g_is64 ? (int)((const long long*)aI)[gr]
                             : ((const int*)aI)[gr];
            s_ai[lr] = idx;
            const char* p = (const char*)(g_Ti + ((size_t)idx << 7));
#pragma unroll
            for (int l = 0; l < 4; l++) pf_l2(p + l * 128);
        }
    }

    ull acc[8][4];
#pragma unroll
    for (int i = 0; i < 8; i++)
#pragma unroll
        for (int j = 0; j < 4; j++) acc[i][j] = 0ull;

    const float4* A4 = (const float4*)A;

    // ---- two K-chunks of 32 ----
#pragma unroll 1
    for (int kb = 0; kb < 2; kb++) {
        const int kbase = kb * 32;
        if (kb) __syncthreads();   // previous chunk's compute done
        // stage At: task q -> row r (32 distinct per warp), kc4 = q>>6
#pragma unroll
        for (int it = 0; it < 4; it++) {
            int q = it * 128 + t;                        // 0..511
            int r = (q & 31) + 32 * ((q >> 5) & 1);      // 0..63
            int kc4 = q >> 6;                            // 0..7
            int gr = min(row0 + r, M - 1);
            float4 v = A4[(size_t)gr * 16 + (kbase >> 2) + kc4];
            At[(kc4 * 4 + 0) * ATS + r] = v.x;
            At[(kc4 * 4 + 1) * ATS + r] = v.y;
            At[(kc4 * 4 + 2) * ATS + r] = v.z;
            At[(kc4 * 4 + 3) * ATS + r] = v.w;
        }
        __syncthreads();

#pragma unroll 4
        for (int kk = 0; kk < 32; kk++) {
            const int k = kbase + kk;
            const float4* a4 = (const float4*)(At + kk * ATS + r0);
            float4 a0 = a4[0], a1 = a4[1];
            ulonglong2 bA = *(const ulonglong2*)(Bs + k * 128 + tx * 4);
            ulonglong2 bB = *(const ulonglong2*)(Bs + k * 128 + 64 + tx * 4);
#pragma unroll
            for (int i = 0; i < 8; i++) {
                float av = (i == 0) ? a0.x : (i == 1) ? a0.y : (i == 2) ? a0.z
                         : (i == 3) ? a0.w : (i == 4) ? a1.x : (i == 5) ? a1.y
                         : (i == 6) ? a1.z : a1.w;
                ull ad = pk2(av, av);
                acc[i][0] = fma2_(ad, bA.x, acc[i][0]);
                acc[i][1] = fma2_(ad, bA.y, acc[i][1]);
                acc[i][2] = fma2_(ad, bB.x, acc[i][2]);
                acc[i][3] = fma2_(ad, bB.y, acc[i][3]);
            }
        }
    }

    // ---- epilogue ----
#pragma unroll
    for (int i = 0; i < 8; i++) {
        int lr = r0 + i;
        int gr = row0 + lr;
        if (gr >= M) continue;
        float2 p0 = upk2(acc[i][0]), p1 = upk2(acc[i][1]);
        float2 p2 = upk2(acc[i][2]), p3 = upk2(acc[i][3]);
        if (MODE == 2) {
            const float4* tu = (const float4*)(g_Tu + ((size_t)s_au[lr] << 7) + c0);
            const float4* ti = (const float4*)(g_Ti + ((size_t)s_ai[lr] << 7) + c0);
            float4 u0 = tu[0], u1 = tu[1];
            float4 v0 = ti[0], v1 = ti[1];
            float4 o0, o1;
            o0.x = fmaxf(p0.x + u0.x + v0.x, 0.f);
            o0.y = fmaxf(p0.y + u0.y + v0.y, 0.f);
            o0.z = fmaxf(p1.x + u0.z + v0.z, 0.f);
            o0.w = fmaxf(p1.y + u0.w + v0.w, 0.f);
            o1.x = fmaxf(p2.x + u1.x + v1.x, 0.f);
            o1.y = fmaxf(p2.y + u1.y + v1.y, 0.f);
            o1.z = fmaxf(p3.x + u1.z + v1.z, 0.f);
            o1.w = fmaxf(p3.y + u1.w + v1.w, 0.f);
            float4* dst = (float4*)(Cout + ((size_t)gr << 7) + c0);
            dst[0] = o0; dst[1] = o1;
        } else {
            float* T = (MODE == 0) ? g_Ti : g_Tu;
            float4 o0 = make_float4(p0.x, p0.y, p1.x, p1.y);
            float4 o1 = make_float4(p2.x, p2.y, p3.x, p3.y);
            float4* dst = (float4*)(T + ((size_t)gr << 7) + c0);
            dst[0] = o0; dst[1] = o1;
        }
    }
}

// ---------------- launch ----------------
extern "C" void kernel_launch(void* const* d_in, const int* in_sizes, int n_in,
                              void* d_out, int out_size) {
    // classify inputs by element count (robust to metadata ordering)
    const float *review = nullptr, *user = nullptr, *item = nullptr, *W = nullptr;
    const void *adjA = nullptr, *adjB = nullptr;
    int n_r = 1000000, n_u = 500000, n_i = 100000;
    for (int k = 0; k < n_in; k++) {
        long long sz = in_sizes[k];
        if (sz == 64000000)      { review = (const float*)d_in[k]; n_r = (int)(sz / 64); }
        else if (sz == 32000000) { user   = (const float*)d_in[k]; n_u = (int)(sz / 64); }
        else if (sz == 6400000)  { item   = (const float*)d_in[k]; n_i = (int)(sz / 64); }
        else if (sz == 24576)    { W      = (const float*)d_in[k]; }
        else if (!adjA)          { adjA   = d_in[k]; }
        else                     { adjB   = d_in[k]; }
    }
    // fallback to declared order if classification failed
    if (!review || !user || !item || !W || !adjA || !adjB) {
        review = (const float*)d_in[0]; user = (const float*)d_in[1];
        item   = (const float*)d_in[2]; W    = (const float*)d_in[3];
        adjA   = d_in[4];               adjB = d_in[5];
        n_r = in_sizes[0] / 64; n_u = in_sizes[1] / 64; n_i = in_sizes[2] / 64;
    }
    float* out = (float*)d_out;

    k_build_wp<<<1, 256>>>(W, adjA);
    k_gemm<0><<<(n_i + 63) / 64, 128>>>(item,   n_i, nullptr, nullptr, nullptr);
    k_gemm<1><<<(n_u + 63) / 64, 128>>>(user,   n_u, nullptr, nullptr, nullptr);
    k_gemm<2><<<(n_r + 63) / 64, 128>>>(review, n_r, out,     adjA,    adjB);
}